// round 1
// baseline (speedup 1.0000x reference)
#include <cuda_runtime.h>

#define N_SRC  10000
#define N_DST  40000
#define NE     1280000
#define IN_DIM 128
#define D      64
#define FEAT   64
#define O_DIM  300

typedef unsigned long long u64;

// ---- scratch (static __device__ — no allocations anywhere) ----
__device__ __align__(16) float g_zsrc[N_SRC * D];   // 2.56 MB
__device__ __align__(16) float g_zdst[N_DST * D];   // 10.24 MB
__device__ float        g_e[NE];                    // 5.12 MB
__device__ unsigned int g_menc[N_DST];
__device__ float        g_denom[N_DST];

// ---- packed f32x2 helpers (sm_100+ FFMA2 path) ----
__device__ __forceinline__ u64 pack2(float lo, float hi) {
    u64 r; asm("mov.b64 %0, {%1, %2};" : "=l"(r) : "f"(lo), "f"(hi)); return r;
}
__device__ __forceinline__ void unpack2(u64 v, float& lo, float& hi) {
    asm("mov.b64 {%0, %1}, %2;" : "=f"(lo), "=f"(hi) : "l"(v));
}
__device__ __forceinline__ u64 fma2(u64 a, u64 b, u64 c) {
    u64 d; asm("fma.rn.f32x2 %0, %1, %2, %3;" : "=l"(d) : "l"(a), "l"(b), "l"(c)); return d;
}
__device__ __forceinline__ u64 add2(u64 a, u64 b) {
    u64 d; asm("add.rn.f32x2 %0, %1, %2;" : "=l"(d) : "l"(a), "l"(b)); return d;
}
__device__ __forceinline__ void red_add4(float* p, float a, float b, float c, float d) {
    asm volatile("red.global.add.v4.f32 [%0], {%1, %2, %3, %4};"
                 :: "l"(p), "f"(a), "f"(b), "f"(c), "f"(d) : "memory");
}

// ============================================================================
// K1/K2: C[M,64] = A[M,K] @ B[K,64], one thread per row, 32 f32x2 accumulators.
// which==0 -> writes g_zsrc, which==1 -> writes g_zdst (keeps symbols device-side).
// ============================================================================
__global__ void __launch_bounds__(128) rowgemm_n64(const float* __restrict__ A,
                                                   const float* __restrict__ B,
                                                   int M, int K, int which) {
    __shared__ __align__(16) float As[128][33];  // pad -> conflict-free row reads
    __shared__ __align__(16) float Bs[32][64];
    float* C = which ? g_zdst : g_zsrc;
    int row = blockIdx.x * 128 + threadIdx.x;

    u64 acc[32];
#pragma unroll
    for (int i = 0; i < 32; i++) acc[i] = 0ull;

    for (int k0 = 0; k0 < K; k0 += 32) {
        __syncthreads();
        for (int idx = threadIdx.x; idx < 128 * 32; idx += 128) {
            int r = idx >> 5, c = idx & 31;
            int gr = blockIdx.x * 128 + r, gc = k0 + c;
            As[r][c] = (gr < M && gc < K) ? A[gr * K + gc] : 0.f;
        }
        for (int idx = threadIdx.x; idx < 32 * 64; idx += 128) {
            int r = idx >> 6, c = idx & 63;
            int gk = k0 + r;
            Bs[r][c] = (gk < K) ? B[gk * 64 + c] : 0.f;
        }
        __syncthreads();
#pragma unroll 4
        for (int kk = 0; kk < 32; kk++) {
            float t = As[threadIdx.x][kk];
            u64 tt = pack2(t, t);
            const ulonglong2* br = reinterpret_cast<const ulonglong2*>(&Bs[kk][0]);
#pragma unroll
            for (int i = 0; i < 16; i++) {
                ulonglong2 w = br[i];
                acc[2 * i]     = fma2(tt, w.x, acc[2 * i]);
                acc[2 * i + 1] = fma2(tt, w.y, acc[2 * i + 1]);
            }
        }
    }
    if (row < M) {
        u64* out = reinterpret_cast<u64*>(C + row * D);
#pragma unroll
        for (int i = 0; i < 32; i++) out[i] = acc[i];
    }
}

// ============================================================================
// K3: per-edge logits. One thread = one edge. dfeat = tfidf[e] @ W_feat done
// as 32 f32x2 accumulators; epilogue gathers z_src[src]+z_dst[dst] (L2-resident),
// adds bias, leaky-relu, dots with W_attn -> g_e[e].
// ============================================================================
__global__ void __launch_bounds__(128) edge_logits(const float* __restrict__ tfidf,
                                                   const float* __restrict__ W_feat,
                                                   const float* __restrict__ b_feat,
                                                   const float* __restrict__ W_attn,
                                                   const int* __restrict__ esrc,
                                                   const int* __restrict__ edst) {
    __shared__ __align__(16) float Ws[FEAT][D];   // 16 KB
    __shared__ float Ts[128][33];                 // 16.9 KB, padded
    __shared__ float bsh[D], wah[D];

    int tid = threadIdx.x;
    for (int idx = tid; idx < FEAT * D; idx += 128)
        Ws[idx >> 6][idx & 63] = W_feat[idx];
    if (tid < D) { bsh[tid] = b_feat[tid]; wah[tid] = W_attn[tid]; }

    int e = blockIdx.x * 128 + tid;
    u64 acc[32];
#pragma unroll
    for (int i = 0; i < 32; i++) acc[i] = 0ull;

    for (int half = 0; half < 2; half++) {
        __syncthreads();
        int f0 = half * 32;
        for (int idx = tid; idx < 128 * 32; idx += 128) {
            int r = idx >> 5, c = idx & 31;
            int ge = blockIdx.x * 128 + r;
            Ts[r][c] = (ge < NE) ? tfidf[ge * FEAT + f0 + c] : 0.f;
        }
        __syncthreads();
#pragma unroll 4
        for (int f = 0; f < 32; f++) {
            float t = Ts[tid][f];
            u64 tt = pack2(t, t);
            const ulonglong2* wr = reinterpret_cast<const ulonglong2*>(&Ws[f0 + f][0]);
#pragma unroll
            for (int i = 0; i < 16; i++) {
                ulonglong2 w = wr[i];
                acc[2 * i]     = fma2(tt, w.x, acc[2 * i]);
                acc[2 * i + 1] = fma2(tt, w.y, acc[2 * i + 1]);
            }
        }
    }

    if (e < NE) {
        int s = esrc[e], d = edst[e];
        const ulonglong2* zs = reinterpret_cast<const ulonglong2*>(g_zsrc + s * D);
        const ulonglong2* zd = reinterpret_cast<const ulonglong2*>(g_zdst + d * D);
        float edot = 0.f;
#pragma unroll
        for (int i = 0; i < 16; i++) {
            ulonglong2 a = zs[i], b = zd[i];
            u64 v0 = add2(acc[2 * i],     add2(a.x, b.x));
            u64 v1 = add2(acc[2 * i + 1], add2(a.y, b.y));
            float x0, x1, x2, x3;
            unpack2(v0, x0, x1); unpack2(v1, x2, x3);
            x0 += bsh[4 * i];     x1 += bsh[4 * i + 1];
            x2 += bsh[4 * i + 2]; x3 += bsh[4 * i + 3];
            float l0 = fmaxf(x0, 0.01f * x0), l1 = fmaxf(x1, 0.01f * x1);
            float l2 = fmaxf(x2, 0.01f * x2), l3 = fmaxf(x3, 0.01f * x3);
            edot += l0 * wah[4 * i]     + l1 * wah[4 * i + 1]
                  + l2 * wah[4 * i + 2] + l3 * wah[4 * i + 3];
        }
        g_e[e] = edot;
    }
}

// ============================================================================
// K4: re-init per call (out zeroed, segment stats reset)
// ============================================================================
__global__ void init_kernel(float* __restrict__ out) {
    int i = blockIdx.x * blockDim.x + threadIdx.x;
    if (i < N_DST * D) out[i] = 0.f;
    if (i < N_DST) { g_menc[i] = 0u; g_denom[i] = 0.f; }
}

// K5: segment max via atomicMax on order-preserving uint encoding.
__global__ void seg_max_kernel(const int* __restrict__ edst) {
    int i = blockIdx.x * blockDim.x + threadIdx.x;
    if (i >= NE) return;
    unsigned b = __float_as_uint(g_e[i]);
    unsigned enc = (b & 0x80000000u) ? ~b : (b | 0x80000000u);
    atomicMax(&g_menc[edst[i]], enc);
}

// K6: w = exp(e - m[dst]); denom[dst] += w; out[dst] += w * z_src[src]
__global__ void scatter_out_kernel(const int* __restrict__ esrc,
                                   const int* __restrict__ edst,
                                   float* __restrict__ out) {
    int i = blockIdx.x * blockDim.x + threadIdx.x;
    if (i >= NE) return;
    int d = edst[i], s = esrc[i];
    unsigned u = g_menc[d];
    float m = (u & 0x80000000u) ? __uint_as_float(u & 0x7FFFFFFFu)
                                : __uint_as_float(~u);
    float w = __expf(g_e[i] - m);
    atomicAdd(&g_denom[d], w);
    const float4* zs = reinterpret_cast<const float4*>(g_zsrc + s * D);
    float* od = out + d * D;
#pragma unroll
    for (int j = 0; j < 16; j++) {
        float4 z = zs[j];
        red_add4(od + 4 * j, w * z.x, w * z.y, w * z.z, w * z.w);
    }
}

// K7: normalize
__global__ void norm_kernel(float* __restrict__ out) {
    int i = blockIdx.x * blockDim.x + threadIdx.x;
    if (i < N_DST * D)
        out[i] = out[i] / fmaxf(g_denom[i >> 6], 1e-9f);
}

// ============================================================================
extern "C" void kernel_launch(void* const* d_in, const int* in_sizes, int n_in,
                              void* d_out, int out_size) {
    const float* h      = (const float*)d_in[0];
    const float* o      = (const float*)d_in[1];
    const float* tfidf  = (const float*)d_in[2];
    const float* W_fc   = (const float*)d_in[3];
    const float* W_fc1  = (const float*)d_in[4];
    const float* W_feat = (const float*)d_in[5];
    const float* b_feat = (const float*)d_in[6];
    const float* W_attn = (const float*)d_in[7];
    const int*   esrc   = (const int*)d_in[8];
    const int*   edst   = (const int*)d_in[9];
    float* out = (float*)d_out;

    init_kernel<<<(N_DST * D + 255) / 256, 256>>>(out);
    rowgemm_n64<<<(N_SRC + 127) / 128, 128>>>(h, W_fc, N_SRC, IN_DIM, 0);
    rowgemm_n64<<<(N_DST + 127) / 128, 128>>>(o, W_fc1, N_DST, O_DIM, 1);
    edge_logits<<<NE / 128, 128>>>(tfidf, W_feat, b_feat, W_attn, esrc, edst);
    seg_max_kernel<<<(NE + 255) / 256, 256>>>(edst);
    scatter_out_kernel<<<(NE + 255) / 256, 256>>>(esrc, edst, out);
    norm_kernel<<<(N_DST * D + 255) / 256, 256>>>(out);
}

// round 2
// speedup vs baseline: 1.4257x; 1.4257x over previous
#include <cuda_runtime.h>

#define N_SRC  10000
#define N_DST  40000
#define NE     1280000
#define IN_DIM 128
#define D      64
#define FEAT   64
#define O_DIM  300

typedef unsigned long long u64;

// ---- scratch (static __device__ — no allocations anywhere) ----
__device__ __align__(16) float g_zsrc[N_SRC * D];   // 2.56 MB
__device__ __align__(16) float g_zdst[N_DST * D];   // 10.24 MB
__device__ float        g_e[NE];                    // 5.12 MB
__device__ unsigned int g_menc[N_DST];
__device__ float        g_denom[N_DST];

// ---- packed f32x2 helpers ----
__device__ __forceinline__ u64 pack2(float lo, float hi) {
    u64 r; asm("mov.b64 %0, {%1, %2};" : "=l"(r) : "f"(lo), "f"(hi)); return r;
}
__device__ __forceinline__ void unpack2(u64 v, float& lo, float& hi) {
    asm("mov.b64 {%0, %1}, %2;" : "=f"(lo), "=f"(hi) : "l"(v));
}
__device__ __forceinline__ u64 fma2(u64 a, u64 b, u64 c) {
    u64 d; asm("fma.rn.f32x2 %0, %1, %2, %3;" : "=l"(d) : "l"(a), "l"(b), "l"(c)); return d;
}
__device__ __forceinline__ u64 add2(u64 a, u64 b) {
    u64 d; asm("add.rn.f32x2 %0, %1, %2;" : "=l"(d) : "l"(a), "l"(b)); return d;
}
__device__ __forceinline__ void red_add4(float* p, float a, float b, float c, float d) {
    asm volatile("red.global.add.v4.f32 [%0], {%1, %2, %3, %4};"
                 :: "l"(p), "f"(a), "f"(b), "f"(c), "f"(d) : "memory");
}

// ============================================================================
// K1/K2: C[M,64] = A[M,K] @ B[K,64], one thread per row. (small cost; kept)
// ============================================================================
__global__ void __launch_bounds__(128) rowgemm_n64(const float* __restrict__ A,
                                                   const float* __restrict__ B,
                                                   int M, int K, int which) {
    __shared__ __align__(16) float As[128][33];
    __shared__ __align__(16) float Bs[32][64];
    float* C = which ? g_zdst : g_zsrc;
    int row = blockIdx.x * 128 + threadIdx.x;

    u64 acc[32];
#pragma unroll
    for (int i = 0; i < 32; i++) acc[i] = 0ull;

    for (int k0 = 0; k0 < K; k0 += 32) {
        __syncthreads();
        for (int idx = threadIdx.x; idx < 128 * 32; idx += 128) {
            int r = idx >> 5, c = idx & 31;
            int gr = blockIdx.x * 128 + r, gc = k0 + c;
            As[r][c] = (gr < M && gc < K) ? A[gr * K + gc] : 0.f;
        }
        for (int idx = threadIdx.x; idx < 32 * 64; idx += 128) {
            int r = idx >> 6, c = idx & 63;
            int gk = k0 + r;
            Bs[r][c] = (gk < K) ? B[gk * 64 + c] : 0.f;
        }
        __syncthreads();
#pragma unroll 4
        for (int kk = 0; kk < 32; kk++) {
            float t = As[threadIdx.x][kk];
            u64 tt = pack2(t, t);
            const ulonglong2* br = reinterpret_cast<const ulonglong2*>(&Bs[kk][0]);
#pragma unroll
            for (int i = 0; i < 16; i++) {
                ulonglong2 w = br[i];
                acc[2 * i]     = fma2(tt, w.x, acc[2 * i]);
                acc[2 * i + 1] = fma2(tt, w.y, acc[2 * i + 1]);
            }
        }
    }
    if (row < M) {
        u64* out = reinterpret_cast<u64*>(C + row * D);
#pragma unroll
        for (int i = 0; i < 32; i++) out[i] = acc[i];
    }
}

// ============================================================================
// K3: edge logits, register-tiled. Block = 128 edges x 64 cols tile.
// Thread (tx=tid&7, ty=tid>>3) owns 8 edges x 8 cols (32 f32x2 accs).
// Per k-step: 4 LDS.128 : 32 FFMA2  ->  FMA-pipe bound.
// Epilogue: gather z, leaky, partial attn-dot, shfl-reduce over tx;
// tx==0 lane writes g_e and does the segment-max atomic inline.
// ============================================================================
__global__ void __launch_bounds__(128) edge_logits(const float* __restrict__ tfidf,
                                                   const float* __restrict__ W_feat,
                                                   const float* __restrict__ b_feat,
                                                   const float* __restrict__ W_attn,
                                                   const int* __restrict__ esrc,
                                                   const int* __restrict__ edst) {
    __shared__ __align__(16) float Ts[FEAT][128];  // transposed tfidf tile: [feat][edge], 32 KB
    __shared__ __align__(16) float Ws[FEAT][D];    // 16 KB

    const int tid   = threadIdx.x;
    const int ebase = blockIdx.x * 128;

    // Load this block's 128 tfidf rows transposed: one edge per thread,
    // stores are lane-consecutive in the edge dim -> conflict-free.
    {
        const float4* src = reinterpret_cast<const float4*>(tfidf + (u64)(ebase + tid) * FEAT);
#pragma unroll
        for (int f4 = 0; f4 < 16; f4++) {
            float4 v = src[f4];
            Ts[4 * f4 + 0][tid] = v.x;
            Ts[4 * f4 + 1][tid] = v.y;
            Ts[4 * f4 + 2][tid] = v.z;
            Ts[4 * f4 + 3][tid] = v.w;
        }
    }
    for (int idx = tid; idx < FEAT * D / 4; idx += 128)
        reinterpret_cast<float4*>(Ws)[idx] = reinterpret_cast<const float4*>(W_feat)[idx];
    __syncthreads();

    const int tx = tid & 7;       // col group (8 cols)
    const int ty = tid >> 3;      // edge group (8 edges)

    u64 acc[8][4];
#pragma unroll
    for (int e = 0; e < 8; e++)
#pragma unroll
        for (int j = 0; j < 4; j++) acc[e][j] = 0ull;

#pragma unroll 4
    for (int f = 0; f < FEAT; f++) {
        float4 a0 = *reinterpret_cast<const float4*>(&Ts[f][ty * 8]);
        float4 a1 = *reinterpret_cast<const float4*>(&Ts[f][ty * 8 + 4]);
        ulonglong2 b0 = *reinterpret_cast<const ulonglong2*>(&Ws[f][tx * 8]);
        ulonglong2 b1 = *reinterpret_cast<const ulonglong2*>(&Ws[f][tx * 8 + 4]);
        u64 bb0 = b0.x, bb1 = b0.y, bb2 = b1.x, bb3 = b1.y;
        float av[8] = {a0.x, a0.y, a0.z, a0.w, a1.x, a1.y, a1.z, a1.w};
#pragma unroll
        for (int e = 0; e < 8; e++) {
            u64 aa = pack2(av[e], av[e]);
            acc[e][0] = fma2(aa, bb0, acc[e][0]);
            acc[e][1] = fma2(aa, bb1, acc[e][1]);
            acc[e][2] = fma2(aa, bb2, acc[e][2]);
            acc[e][3] = fma2(aa, bb3, acc[e][3]);
        }
    }

    // epilogue
    float4 bi0 = *reinterpret_cast<const float4*>(b_feat + tx * 8);
    float4 bi1 = *reinterpret_cast<const float4*>(b_feat + tx * 8 + 4);
    float4 wa0 = *reinterpret_cast<const float4*>(W_attn + tx * 8);
    float4 wa1 = *reinterpret_cast<const float4*>(W_attn + tx * 8 + 4);
    int4 sA = *reinterpret_cast<const int4*>(esrc + ebase + ty * 8);
    int4 sB = *reinterpret_cast<const int4*>(esrc + ebase + ty * 8 + 4);
    int4 dA = *reinterpret_cast<const int4*>(edst + ebase + ty * 8);
    int4 dB = *reinterpret_cast<const int4*>(edst + ebase + ty * 8 + 4);
    int sv[8] = {sA.x, sA.y, sA.z, sA.w, sB.x, sB.y, sB.z, sB.w};
    int dv[8] = {dA.x, dA.y, dA.z, dA.w, dB.x, dB.y, dB.z, dB.w};

#pragma unroll
    for (int k = 0; k < 8; k++) {
        int s = sv[k], d = dv[k];
        const float4* zs = reinterpret_cast<const float4*>(g_zsrc + s * D + tx * 8);
        const float4* zd = reinterpret_cast<const float4*>(g_zdst + d * D + tx * 8);
        float4 zs0 = zs[0], zs1 = zs[1];
        float4 zd0 = zd[0], zd1 = zd[1];

        float df[8];
        unpack2(acc[k][0], df[0], df[1]);
        unpack2(acc[k][1], df[2], df[3]);
        unpack2(acc[k][2], df[4], df[5]);
        unpack2(acc[k][3], df[6], df[7]);

        float x0 = df[0] + zs0.x + zd0.x + bi0.x;
        float x1 = df[1] + zs0.y + zd0.y + bi0.y;
        float x2 = df[2] + zs0.z + zd0.z + bi0.z;
        float x3 = df[3] + zs0.w + zd0.w + bi0.w;
        float x4 = df[4] + zs1.x + zd1.x + bi1.x;
        float x5 = df[5] + zs1.y + zd1.y + bi1.y;
        float x6 = df[6] + zs1.z + zd1.z + bi1.z;
        float x7 = df[7] + zs1.w + zd1.w + bi1.w;

        float p = fmaxf(x0, 0.01f * x0) * wa0.x
                + fmaxf(x1, 0.01f * x1) * wa0.y
                + fmaxf(x2, 0.01f * x2) * wa0.z
                + fmaxf(x3, 0.01f * x3) * wa0.w
                + fmaxf(x4, 0.01f * x4) * wa1.x
                + fmaxf(x5, 0.01f * x5) * wa1.y
                + fmaxf(x6, 0.01f * x6) * wa1.z
                + fmaxf(x7, 0.01f * x7) * wa1.w;

        // reduce over tx (lanes differing in bits 0..2 of lane id)
        p += __shfl_xor_sync(0xffffffffu, p, 1);
        p += __shfl_xor_sync(0xffffffffu, p, 2);
        p += __shfl_xor_sync(0xffffffffu, p, 4);

        if (tx == 0) {
            int e = ebase + ty * 8 + k;
            g_e[e] = p;
            unsigned b = __float_as_uint(p);
            unsigned enc = (b & 0x80000000u) ? ~b : (b | 0x80000000u);
            atomicMax(&g_menc[d], enc);
        }
    }
}

// ============================================================================
// K4: re-init per call
// ============================================================================
__global__ void init_kernel(float* __restrict__ out) {
    int i = blockIdx.x * blockDim.x + threadIdx.x;
    if (i < N_DST * D) out[i] = 0.f;
    if (i < N_DST) { g_menc[i] = 0u; g_denom[i] = 0.f; }
}

// K5: w = exp(e - m[dst]); denom[dst] += w; out[dst] += w * z_src[src]
__global__ void scatter_out_kernel(const int* __restrict__ esrc,
                                   const int* __restrict__ edst,
                                   float* __restrict__ out) {
    int i = blockIdx.x * blockDim.x + threadIdx.x;
    if (i >= NE) return;
    int d = edst[i], s = esrc[i];
    unsigned u = g_menc[d];
    float m = (u & 0x80000000u) ? __uint_as_float(u & 0x7FFFFFFFu)
                                : __uint_as_float(~u);
    float w = __expf(g_e[i] - m);
    atomicAdd(&g_denom[d], w);
    const float4* zs = reinterpret_cast<const float4*>(g_zsrc + s * D);
    float* od = out + d * D;
#pragma unroll
    for (int j = 0; j < 16; j++) {
        float4 z = zs[j];
        red_add4(od + 4 * j, w * z.x, w * z.y, w * z.z, w * z.w);
    }
}

// K6: normalize
__global__ void norm_kernel(float* __restrict__ out) {
    int i = blockIdx.x * blockDim.x + threadIdx.x;
    if (i < N_DST * D)
        out[i] = out[i] / fmaxf(g_denom[i >> 6], 1e-9f);
}

// ============================================================================
extern "C" void kernel_launch(void* const* d_in, const int* in_sizes, int n_in,
                              void* d_out, int out_size) {
    const float* h      = (const float*)d_in[0];
    const float* o      = (const float*)d_in[1];
    const float* tfidf  = (const float*)d_in[2];
    const float* W_fc   = (const float*)d_in[3];
    const float* W_fc1  = (const float*)d_in[4];
    const float* W_feat = (const float*)d_in[5];
    const float* b_feat = (const float*)d_in[6];
    const float* W_attn = (const float*)d_in[7];
    const int*   esrc   = (const int*)d_in[8];
    const int*   edst   = (const int*)d_in[9];
    float* out = (float*)d_out;

    init_kernel<<<(N_DST * D + 255) / 256, 256>>>(out);
    rowgemm_n64<<<(N_SRC + 127) / 128, 128>>>(h, W_fc, N_SRC, IN_DIM, 0);
    rowgemm_n64<<<(N_DST + 127) / 128, 128>>>(o, W_fc1, N_DST, O_DIM, 1);
    edge_logits<<<NE / 128, 128>>>(tfidf, W_feat, b_feat, W_attn, esrc, edst);
    scatter_out_kernel<<<(NE + 255) / 256, 256>>>(esrc, edst, out);
    norm_kernel<<<(N_DST * D + 255) / 256, 256>>>(out);
}

// round 3
// speedup vs baseline: 2.0679x; 1.4504x over previous
#include <cuda_runtime.h>

#define N_SRC  10000
#define N_DST  40000
#define NE     1280000
#define IN_DIM 128
#define D      64
#define FEAT   64
#define O_DIM  300

typedef unsigned long long u64;
typedef unsigned int u32;

// ---- scratch (static __device__ — no allocations anywhere) ----
__device__ __align__(16) float g_zsrc[N_SRC * D];   // 2.56 MB
__device__ __align__(16) float g_zdst[N_DST * D];   // 10.24 MB
__device__ float        g_e[NE];                    // 5.12 MB
__device__ unsigned int g_menc[N_DST];
__device__ float        g_denom[N_DST];

// ---- helpers ----
__device__ __forceinline__ u64 pack2(float lo, float hi) {
    u64 r; asm("mov.b64 %0, {%1, %2};" : "=l"(r) : "f"(lo), "f"(hi)); return r;
}
__device__ __forceinline__ u64 fma2(u64 a, u64 b, u64 c) {
    u64 d; asm("fma.rn.f32x2 %0, %1, %2, %3;" : "=l"(d) : "l"(a), "l"(b), "l"(c)); return d;
}
__device__ __forceinline__ void red_add4(float* p, float a, float b, float c, float d) {
    asm volatile("red.global.add.v4.f32 [%0], {%1, %2, %3, %4};"
                 :: "l"(p), "f"(a), "f"(b), "f"(c), "f"(d) : "memory");
}
__device__ __forceinline__ u32 cvt_tf32(float x) {
    u32 u; asm("cvt.rna.tf32.f32 %0, %1;" : "=r"(u) : "f"(x)); return u;
}
__device__ __forceinline__ uint4 cvt4(float4 v) {
    uint4 w; w.x = cvt_tf32(v.x); w.y = cvt_tf32(v.y);
    w.z = cvt_tf32(v.z); w.w = cvt_tf32(v.w); return w;
}
__device__ __forceinline__ void mma_tf32(float c[4], u32 a0, u32 a1, u32 a2, u32 a3,
                                         u32 b0, u32 b1) {
    asm("mma.sync.aligned.m16n8k8.row.col.f32.tf32.tf32.f32 "
        "{%0,%1,%2,%3}, {%4,%5,%6,%7}, {%8,%9}, {%0,%1,%2,%3};"
        : "+f"(c[0]), "+f"(c[1]), "+f"(c[2]), "+f"(c[3])
        : "r"(a0), "r"(a1), "r"(a2), "r"(a3), "r"(b0), "r"(b1));
}

// ============================================================================
// K1: z_src = h @ W_fc, full fp32 (feeds the output directly). M=10000, K=128.
// ============================================================================
__global__ void __launch_bounds__(128) rowgemm_zsrc(const float* __restrict__ A,
                                                    const float* __restrict__ B,
                                                    int M, int K) {
    __shared__ __align__(16) float As[128][33];
    __shared__ __align__(16) float Bs[32][64];
    int row = blockIdx.x * 128 + threadIdx.x;
    u64 acc[32];
#pragma unroll
    for (int i = 0; i < 32; i++) acc[i] = 0ull;

    for (int k0 = 0; k0 < K; k0 += 32) {
        __syncthreads();
        for (int idx = threadIdx.x; idx < 128 * 32; idx += 128) {
            int r = idx >> 5, c = idx & 31;
            int gr = blockIdx.x * 128 + r, gc = k0 + c;
            As[r][c] = (gr < M && gc < K) ? A[gr * K + gc] : 0.f;
        }
        for (int idx = threadIdx.x; idx < 32 * 64; idx += 128) {
            int r = idx >> 6, c = idx & 63;
            int gk = k0 + r;
            Bs[r][c] = (gk < K) ? B[gk * 64 + c] : 0.f;
        }
        __syncthreads();
#pragma unroll 4
        for (int kk = 0; kk < 32; kk++) {
            float t = As[threadIdx.x][kk];
            u64 tt = pack2(t, t);
            const ulonglong2* br = reinterpret_cast<const ulonglong2*>(&Bs[kk][0]);
#pragma unroll
            for (int i = 0; i < 16; i++) {
                ulonglong2 w = br[i];
                acc[2 * i]     = fma2(tt, w.x, acc[2 * i]);
                acc[2 * i + 1] = fma2(tt, w.y, acc[2 * i + 1]);
            }
        }
    }
    if (row < M) {
        u64* out = reinterpret_cast<u64*>(g_zsrc + row * D);
#pragma unroll
        for (int i = 0; i < 32; i++) out[i] = acc[i];
    }
}

// ============================================================================
// K2: z_dst = o @ W_fc1 via tf32 mma. C[M,64] = A[M,K]@B[K,64], K padded to 64s.
// Block: 256 thr / 8 warps; tile 64 rows; warp (eg=w>>1, nh=w&1) -> 16 rows x 32 cols.
// ============================================================================
__global__ void __launch_bounds__(256) gemm_tf32_zdst(const float* __restrict__ A,
                                                      const float* __restrict__ B,
                                                      int M, int K) {
    __shared__ u32 Ts[64][68];   // tf32 A tile  (stride 68: frag banks 4g+tg unique)
    __shared__ u32 Bs[64][72];   // tf32 B tile  (stride 72: frag banks 8tg+g unique)

    const int tid  = threadIdx.x;
    const int warp = tid >> 5, lane = tid & 31;
    const int g = lane >> 2, tg = lane & 3;
    const int eg = warp >> 1, nh = warp & 1;
    const int rbase = blockIdx.x * 64;
    const int Kf4 = K >> 2;                 // K divisible by 4 (300/4=75)

    float acc[4][4];
#pragma unroll
    for (int nt = 0; nt < 4; nt++)
#pragma unroll
        for (int j = 0; j < 4; j++) acc[nt][j] = 0.f;

    const int KO = (K + 63) / 64;
    for (int ko = 0; ko < KO; ko++) {
        __syncthreads();
        // stage A[64 x 64] (zero-pad OOB)
#pragma unroll
        for (int j = 0; j < 4; j++) {
            int idx = tid + j * 256;        // f4 units, 1024 total
            int r = idx >> 4, c4 = idx & 15;
            int gr = rbase + r, gf4 = ko * 16 + c4;
            float4 v = make_float4(0.f, 0.f, 0.f, 0.f);
            if (gr < M && gf4 < Kf4)
                v = reinterpret_cast<const float4*>(A + (u64)gr * K)[gf4];
            *reinterpret_cast<uint4*>(&Ts[r][c4 * 4]) = cvt4(v);
        }
        // stage B[64 x 64]
#pragma unroll
        for (int j = 0; j < 4; j++) {
            int idx = tid + j * 256;
            int r = idx >> 4, c4 = idx & 15;
            int gk = ko * 64 + r;
            float4 v = make_float4(0.f, 0.f, 0.f, 0.f);
            if (gk < K)
                v = reinterpret_cast<const float4*>(B + gk * 64)[c4];
            *reinterpret_cast<uint4*>(&Bs[r][c4 * 4]) = cvt4(v);
        }
        __syncthreads();

        const int m0 = eg * 16;
#pragma unroll
        for (int kc = 0; kc < 8; kc++) {
            int k = kc * 8;
            u32 a0 = Ts[m0 + g][k + tg];
            u32 a1 = Ts[m0 + 8 + g][k + tg];
            u32 a2 = Ts[m0 + g][k + tg + 4];
            u32 a3 = Ts[m0 + 8 + g][k + tg + 4];
#pragma unroll
            for (int nt = 0; nt < 4; nt++) {
                int n0 = nh * 32 + nt * 8 + g;
                u32 b0 = Bs[k + tg][n0];
                u32 b1 = Bs[k + tg + 4][n0];
                mma_tf32(acc[nt], a0, a1, a2, a3, b0, b1);
            }
        }
    }

    // epilogue: write 16x32 per warp
#pragma unroll
    for (int rh = 0; rh < 2; rh++) {
        int row = rbase + eg * 16 + rh * 8 + g;
        if (row < M) {
#pragma unroll
            for (int nt = 0; nt < 4; nt++) {
                int col = nh * 32 + nt * 8 + 2 * tg;
                float2 v = make_float2(acc[nt][rh * 2], acc[nt][rh * 2 + 1]);
                *reinterpret_cast<float2*>(g_zdst + row * D + col) = v;
            }
        }
    }
}

// ============================================================================
// K3: edge logits via tf32 mma + fused epilogue (gather z, leaky, attn dot,
// segment-max atomic inline). Block: 256 thr, tile 64 edges x 64 cols, K=64.
// ============================================================================
__global__ void __launch_bounds__(256) edge_logits_tc(const float* __restrict__ tfidf,
                                                      const float* __restrict__ W_feat,
                                                      const float* __restrict__ b_feat,
                                                      const float* __restrict__ W_attn,
                                                      const int* __restrict__ esrc,
                                                      const int* __restrict__ edst) {
    __shared__ u32 Ts[64][68];
    __shared__ u32 Bs[64][72];
    __shared__ float Part[64][2];

    const int tid  = threadIdx.x;
    const int warp = tid >> 5, lane = tid & 31;
    const int g = lane >> 2, tg = lane & 3;
    const int eg = warp >> 1, nh = warp & 1;
    const int ebase = blockIdx.x * 64;

    // stage tfidf tile (contiguous 64*64 floats) as tf32
    {
        const float4* src = reinterpret_cast<const float4*>(tfidf + (u64)ebase * FEAT);
#pragma unroll
        for (int j = 0; j < 4; j++) {
            int idx = tid + j * 256;
            int r = idx >> 4, c4 = idx & 15;
            *reinterpret_cast<uint4*>(&Ts[r][c4 * 4]) = cvt4(src[idx]);
        }
    }
    // stage W_feat as tf32
    {
        const float4* src = reinterpret_cast<const float4*>(W_feat);
#pragma unroll
        for (int j = 0; j < 4; j++) {
            int idx = tid + j * 256;
            int r = idx >> 4, c4 = idx & 15;
            *reinterpret_cast<uint4*>(&Bs[r][c4 * 4]) = cvt4(src[idx]);
        }
    }
    __syncthreads();

    float acc[4][4];
#pragma unroll
    for (int nt = 0; nt < 4; nt++)
#pragma unroll
        for (int j = 0; j < 4; j++) acc[nt][j] = 0.f;

    const int m0 = eg * 16;
#pragma unroll
    for (int kc = 0; kc < 8; kc++) {
        int k = kc * 8;
        u32 a0 = Ts[m0 + g][k + tg];
        u32 a1 = Ts[m0 + 8 + g][k + tg];
        u32 a2 = Ts[m0 + g][k + tg + 4];
        u32 a3 = Ts[m0 + 8 + g][k + tg + 4];
#pragma unroll
        for (int nt = 0; nt < 4; nt++) {
            int n0 = nh * 32 + nt * 8 + g;
            u32 b0 = Bs[k + tg][n0];
            u32 b1 = Bs[k + tg + 4][n0];
            mma_tf32(acc[nt], a0, a1, a2, a3, b0, b1);
        }
    }

    // fused epilogue
    float2 bf[4], wa[4];
#pragma unroll
    for (int nt = 0; nt < 4; nt++) {
        int col = nh * 32 + nt * 8 + 2 * tg;
        bf[nt] = *reinterpret_cast<const float2*>(b_feat + col);
        wa[nt] = *reinterpret_cast<const float2*>(W_attn + col);
    }

#pragma unroll
    for (int rh = 0; rh < 2; rh++) {
        int rl = eg * 16 + rh * 8 + g;
        int e  = ebase + rl;
        int s = esrc[e], d = edst[e];
        const float* zsp = g_zsrc + s * D;
        const float* zdp = g_zdst + d * D;
        float p = 0.f;
#pragma unroll
        for (int nt = 0; nt < 4; nt++) {
            int col = nh * 32 + nt * 8 + 2 * tg;
            float2 zs = *reinterpret_cast<const float2*>(zsp + col);
            float2 zd = *reinterpret_cast<const float2*>(zdp + col);
            float x0 = acc[nt][rh * 2]     + zs.x + zd.x + bf[nt].x;
            float x1 = acc[nt][rh * 2 + 1] + zs.y + zd.y + bf[nt].y;
            p += fmaxf(x0, 0.01f * x0) * wa[nt].x
               + fmaxf(x1, 0.01f * x1) * wa[nt].y;
        }
        p += __shfl_xor_sync(0xffffffffu, p, 1);
        p += __shfl_xor_sync(0xffffffffu, p, 2);
        if (tg == 0) Part[rl][nh] = p;
    }
    __syncthreads();

    if (tid < 64) {
        float p = Part[tid][0] + Part[tid][1];
        int e = ebase + tid;
        g_e[e] = p;
        int d = edst[e];
        unsigned b = __float_as_uint(p);
        unsigned enc = (b & 0x80000000u) ? ~b : (b | 0x80000000u);
        atomicMax(&g_menc[d], enc);
    }
}

// ============================================================================
// K4: re-init per call
// ============================================================================
__global__ void init_kernel(float* __restrict__ out) {
    int i = blockIdx.x * blockDim.x + threadIdx.x;
    if (i < N_DST * D) out[i] = 0.f;
    if (i < N_DST) { g_menc[i] = 0u; g_denom[i] = 0.f; }
}

// K5: w = exp(e - m[dst]); denom[dst] += w; out[dst] += w * z_src[src]
__global__ void scatter_out_kernel(const int* __restrict__ esrc,
                                   const int* __restrict__ edst,
                                   float* __restrict__ out) {
    int i = blockIdx.x * blockDim.x + threadIdx.x;
    if (i >= NE) return;
    int d = edst[i], s = esrc[i];
    unsigned u = g_menc[d];
    float m = (u & 0x80000000u) ? __uint_as_float(u & 0x7FFFFFFFu)
                                : __uint_as_float(~u);
    float w = __expf(g_e[i] - m);
    atomicAdd(&g_denom[d], w);
    const float4* zs = reinterpret_cast<const float4*>(g_zsrc + s * D);
    float* od = out + d * D;
#pragma unroll
    for (int j = 0; j < 16; j++) {
        float4 z = zs[j];
        red_add4(od + 4 * j, w * z.x, w * z.y, w * z.z, w * z.w);
    }
}

// K6: normalize
__global__ void norm_kernel(float* __restrict__ out) {
    int i = blockIdx.x * blockDim.x + threadIdx.x;
    if (i < N_DST * D)
        out[i] = out[i] / fmaxf(g_denom[i >> 6], 1e-9f);
}

// ============================================================================
extern "C" void kernel_launch(void* const* d_in, const int* in_sizes, int n_in,
                              void* d_out, int out_size) {
    const float* h      = (const float*)d_in[0];
    const float* o      = (const float*)d_in[1];
    const float* tfidf  = (const float*)d_in[2];
    const float* W_fc   = (const float*)d_in[3];
    const float* W_fc1  = (const float*)d_in[4];
    const float* W_feat = (const float*)d_in[5];
    const float* b_feat = (const float*)d_in[6];
    const float* W_attn = (const float*)d_in[7];
    const int*   esrc   = (const int*)d_in[8];
    const int*   edst   = (const int*)d_in[9];
    float* out = (float*)d_out;

    init_kernel<<<(N_DST * D + 255) / 256, 256>>>(out);
    rowgemm_zsrc<<<(N_SRC + 127) / 128, 128>>>(h, W_fc, N_SRC, IN_DIM);
    gemm_tf32_zdst<<<(N_DST + 63) / 64, 256>>>(o, W_fc1, N_DST, O_DIM);
    edge_logits_tc<<<NE / 64, 256>>>(tfidf, W_feat, b_feat, W_attn, esrc, edst);
    scatter_out_kernel<<<(NE + 255) / 256, 256>>>(esrc, edst, out);
    norm_kernel<<<(N_DST * D + 255) / 256, 256>>>(out);
}

// round 4
// speedup vs baseline: 2.6667x; 1.2896x over previous
#include <cuda_runtime.h>

#define N_SRC  10000
#define N_DST  40000
#define NE     1280000
#define IN_DIM 128
#define D      64
#define FEAT   64
#define O_DIM  300

typedef unsigned long long u64;
typedef unsigned int u32;

// ---- scratch (static __device__ — no allocations anywhere) ----
__device__ __align__(16) float g_zsrc[N_SRC * D];   // 2.56 MB
__device__ __align__(16) float g_zdst[N_DST * D];   // 10.24 MB
__device__ float g_e[NE];                           // 5.12 MB
__device__ __align__(16) float g_WT[FEAT * D];      // W_feat transposed [n][k]
__device__ int g_hist[N_DST];
__device__ int g_cursor[N_DST];
__device__ int g_rowstart[N_DST + 1];
__device__ int g_csr[NE];                           // 5.12 MB

// ---- helpers ----
__device__ __forceinline__ u64 pack2(float lo, float hi) {
    u64 r; asm("mov.b64 %0, {%1, %2};" : "=l"(r) : "f"(lo), "f"(hi)); return r;
}
__device__ __forceinline__ u64 fma2(u64 a, u64 b, u64 c) {
    u64 d; asm("fma.rn.f32x2 %0, %1, %2, %3;" : "=l"(d) : "l"(a), "l"(b), "l"(c)); return d;
}
__device__ __forceinline__ u32 cvt_tf32(float x) {
    u32 u; asm("cvt.rna.tf32.f32 %0, %1;" : "=r"(u) : "f"(x)); return u;
}
__device__ __forceinline__ uint4 cvt4(float4 v) {
    uint4 w; w.x = cvt_tf32(v.x); w.y = cvt_tf32(v.y);
    w.z = cvt_tf32(v.z); w.w = cvt_tf32(v.w); return w;
}
__device__ __forceinline__ void mma_tf32(float c[4], u32 a0, u32 a1, u32 a2, u32 a3,
                                         u32 b0, u32 b1) {
    asm("mma.sync.aligned.m16n8k8.row.col.f32.tf32.tf32.f32 "
        "{%0,%1,%2,%3}, {%4,%5,%6,%7}, {%8,%9}, {%0,%1,%2,%3};"
        : "+f"(c[0]), "+f"(c[1]), "+f"(c[2]), "+f"(c[3])
        : "r"(a0), "r"(a1), "r"(a2), "r"(a3), "r"(b0), "r"(b1));
}
__device__ __forceinline__ void ldsm4(u32& r0, u32& r1, u32& r2, u32& r3, u32 addr) {
    asm volatile("ldmatrix.sync.aligned.m8n8.x4.shared.b16 {%0,%1,%2,%3}, [%4];"
                 : "=r"(r0), "=r"(r1), "=r"(r2), "=r"(r3) : "r"(addr));
}

// ============================================================================
// prep: zero CSR counters; transpose W_feat -> g_WT[n][k]
// ============================================================================
__global__ void prep_kernel(const float* __restrict__ W_feat) {
    int i = blockIdx.x * 256 + threadIdx.x;
    if (i < N_DST) { g_hist[i] = 0; g_cursor[i] = 0; }
    if (i < FEAT * D) g_WT[(i & 63) * 64 + (i >> 6)] = W_feat[i];
}

__global__ void hist_kernel(const int* __restrict__ edst) {
    int i = blockIdx.x * blockDim.x + threadIdx.x;
    if (i < NE) atomicAdd(&g_hist[edst[i]], 1);
}

// single-block exclusive scan of g_hist -> g_rowstart
__global__ void __launch_bounds__(1024) scan_kernel() {
    __shared__ int part[1024];
    const int t = threadIdx.x;
    const int CH = 40;                       // 1024*40 = 40960 >= N_DST
    int own = 0;
    for (int j = 0; j < CH; j++) {
        int idx = t * CH + j;
        if (idx < N_DST) own += g_hist[idx];
    }
    part[t] = own;
    __syncthreads();
    for (int off = 1; off < 1024; off <<= 1) {
        int v = (t >= off) ? part[t - off] : 0;
        __syncthreads();
        part[t] += v;
        __syncthreads();
    }
    int base = part[t] - own;                // exclusive prefix for this chunk
    for (int j = 0; j < CH; j++) {
        int idx = t * CH + j;
        if (idx < N_DST) { g_rowstart[idx] = base; base += g_hist[idx]; }
    }
    if (t == 1023) g_rowstart[N_DST] = part[1023];
}

__global__ void fill_kernel(const int* __restrict__ edst) {
    int i = blockIdx.x * blockDim.x + threadIdx.x;
    if (i >= NE) return;
    int d = edst[i];
    int pos = atomicAdd(&g_cursor[d], 1);
    g_csr[g_rowstart[d] + pos] = i;
}

// ============================================================================
// K1: z_src = h @ W_fc, full fp32 (feeds output directly). M=10000, K=128.
// ============================================================================
__global__ void __launch_bounds__(128) rowgemm_zsrc(const float* __restrict__ A,
                                                    const float* __restrict__ B,
                                                    int M, int K) {
    __shared__ __align__(16) float As[128][33];
    __shared__ __align__(16) float Bs[32][64];
    int row = blockIdx.x * 128 + threadIdx.x;
    u64 acc[32];
#pragma unroll
    for (int i = 0; i < 32; i++) acc[i] = 0ull;

    for (int k0 = 0; k0 < K; k0 += 32) {
        __syncthreads();
        for (int idx = threadIdx.x; idx < 128 * 32; idx += 128) {
            int r = idx >> 5, c = idx & 31;
            int gr = blockIdx.x * 128 + r, gc = k0 + c;
            As[r][c] = (gr < M && gc < K) ? A[gr * K + gc] : 0.f;
        }
        for (int idx = threadIdx.x; idx < 32 * 64; idx += 128) {
            int r = idx >> 6, c = idx & 63;
            int gk = k0 + r;
            Bs[r][c] = (gk < K) ? B[gk * 64 + c] : 0.f;
        }
        __syncthreads();
#pragma unroll 4
        for (int kk = 0; kk < 32; kk++) {
            float t = As[threadIdx.x][kk];
            u64 tt = pack2(t, t);
            const ulonglong2* br = reinterpret_cast<const ulonglong2*>(&Bs[kk][0]);
#pragma unroll
            for (int i = 0; i < 16; i++) {
                ulonglong2 w = br[i];
                acc[2 * i]     = fma2(tt, w.x, acc[2 * i]);
                acc[2 * i + 1] = fma2(tt, w.y, acc[2 * i + 1]);
            }
        }
    }
    if (row < M) {
        u64* out = reinterpret_cast<u64*>(g_zsrc + row * D);
#pragma unroll
        for (int i = 0; i < 32; i++) out[i] = acc[i];
    }
}

// ============================================================================
// K2: z_dst = o @ W_fc1 via tf32 mma (logits-only, tf32 precision OK).
// ============================================================================
__global__ void __launch_bounds__(256) gemm_tf32_zdst(const float* __restrict__ A,
                                                      const float* __restrict__ B,
                                                      int M, int K) {
    __shared__ u32 Ts[64][68];
    __shared__ u32 Bs[64][72];

    const int tid  = threadIdx.x;
    const int warp = tid >> 5, lane = tid & 31;
    const int g = lane >> 2, tg = lane & 3;
    const int eg = warp >> 1, nh = warp & 1;
    const int rbase = blockIdx.x * 64;
    const int Kf4 = K >> 2;

    float acc[4][4];
#pragma unroll
    for (int nt = 0; nt < 4; nt++)
#pragma unroll
        for (int j = 0; j < 4; j++) acc[nt][j] = 0.f;

    const int KO = (K + 63) / 64;
    for (int ko = 0; ko < KO; ko++) {
        __syncthreads();
#pragma unroll
        for (int j = 0; j < 4; j++) {
            int idx = tid + j * 256;
            int r = idx >> 4, c4 = idx & 15;
            int gr = rbase + r, gf4 = ko * 16 + c4;
            float4 v = make_float4(0.f, 0.f, 0.f, 0.f);
            if (gr < M && gf4 < Kf4)
                v = reinterpret_cast<const float4*>(A + (u64)gr * K)[gf4];
            *reinterpret_cast<uint4*>(&Ts[r][c4 * 4]) = cvt4(v);
        }
#pragma unroll
        for (int j = 0; j < 4; j++) {
            int idx = tid + j * 256;
            int r = idx >> 4, c4 = idx & 15;
            int gk = ko * 64 + r;
            float4 v = make_float4(0.f, 0.f, 0.f, 0.f);
            if (gk < K)
                v = reinterpret_cast<const float4*>(B + gk * 64)[c4];
            *reinterpret_cast<uint4*>(&Bs[r][c4 * 4]) = cvt4(v);
        }
        __syncthreads();

        const int m0 = eg * 16;
#pragma unroll
        for (int kc = 0; kc < 8; kc++) {
            int k = kc * 8;
            u32 a0 = Ts[m0 + g][k + tg];
            u32 a1 = Ts[m0 + 8 + g][k + tg];
            u32 a2 = Ts[m0 + g][k + tg + 4];
            u32 a3 = Ts[m0 + 8 + g][k + tg + 4];
#pragma unroll
            for (int nt = 0; nt < 4; nt++) {
                int n0 = nh * 32 + nt * 8 + g;
                u32 b0 = Bs[k + tg][n0];
                u32 b1 = Bs[k + tg + 4][n0];
                mma_tf32(acc[nt], a0, a1, a2, a3, b0, b1);
            }
        }
    }

#pragma unroll
    for (int rh = 0; rh < 2; rh++) {
        int row = rbase + eg * 16 + rh * 8 + g;
        if (row < M) {
#pragma unroll
            for (int nt = 0; nt < 4; nt++) {
                int col = nh * 32 + nt * 8 + 2 * tg;
                float2 v = make_float2(acc[nt][rh * 2], acc[nt][rh * 2 + 1]);
                *reinterpret_cast<float2*>(g_zdst + row * D + col) = v;
            }
        }
    }
}

// ============================================================================
// K3: edge logits. 128 edges/block, 256 thr (8 warps); warp w -> 16 edges x 64 cols.
// All mma operands via ldmatrix.x4 (tf32-as-b16 trick). Fused epilogue.
// Dynamic smem: Ts[128][68] + Bs[64][68] = 52224 B.
// ============================================================================
__global__ void __launch_bounds__(256) edge_logits_tc(const float* __restrict__ tfidf,
                                                      const float* __restrict__ b_feat,
                                                      const float* __restrict__ W_attn,
                                                      const int* __restrict__ esrc,
                                                      const int* __restrict__ edst) {
    extern __shared__ u32 smbuf[];
    u32 (*Ts)[68] = reinterpret_cast<u32(*)[68]>(smbuf);            // [128][68]
    u32 (*Bs)[68] = reinterpret_cast<u32(*)[68]>(smbuf + 128 * 68); // [64][68]

    const int tid  = threadIdx.x;
    const int warp = tid >> 5, lane = tid & 31;
    const int g = lane >> 2, tg = lane & 3;
    const int ebase = blockIdx.x * 128;

    // stage tfidf tile (128 x 64, contiguous) as tf32
    {
        const float4* src = reinterpret_cast<const float4*>(tfidf + (u64)ebase * FEAT);
#pragma unroll
        for (int j = 0; j < 8; j++) {
            int idx = tid + j * 256;
            int r = idx >> 4, c4 = idx & 15;
            *reinterpret_cast<uint4*>(&Ts[r][c4 * 4]) = cvt4(src[idx]);
        }
    }
    // stage W_feat^T (n-major) as tf32
    {
        const float4* wt = reinterpret_cast<const float4*>(g_WT);
#pragma unroll
        for (int j = 0; j < 4; j++) {
            int idx = tid + j * 256;
            int r = idx >> 4, c4 = idx & 15;
            *reinterpret_cast<uint4*>(&Bs[r][c4 * 4]) = cvt4(wt[idx]);
        }
    }
    __syncthreads();

    const int m0 = warp * 16;
    const int q = lane >> 3, r8 = lane & 7;
    // A tiles: q0:(rows m0+r8, k..k+3) q1:(m0+8+r8, k) q2:(m0+r8, k+4) q3:(m0+8+r8, k+4)
    u32 aBase = (u32)__cvta_generic_to_shared(&Ts[m0 + ((q & 1) << 3) + r8][(q >> 1) << 2]);
    // B tiles: q0:(n r8, k) q1:(n r8, k+4) q2:(n 8+r8, k) q3:(n 8+r8, k+4)
    u32 bBase = (u32)__cvta_generic_to_shared(&Bs[((q >> 1) << 3) + r8][(q & 1) << 2]);
    const u32 GSTRIDE = 16 * 68 * 4;

    float acc[8][4];
#pragma unroll
    for (int nt = 0; nt < 8; nt++)
#pragma unroll
        for (int j = 0; j < 4; j++) acc[nt][j] = 0.f;

#pragma unroll
    for (int kc = 0; kc < 8; kc++) {
        u32 ko = kc * 32;  // 8 tf32 cols = 32 bytes
        u32 a0, a1, a2, a3;
        ldsm4(a0, a1, a2, a3, aBase + ko);
#pragma unroll
        for (int G = 0; G < 4; G++) {
            u32 b0, b1, b2, b3;
            ldsm4(b0, b1, b2, b3, bBase + G * GSTRIDE + ko);
            mma_tf32(acc[2 * G],     a0, a1, a2, a3, b0, b1);
            mma_tf32(acc[2 * G + 1], a0, a1, a2, a3, b2, b3);
        }
    }

    // fused epilogue: gather z, bias, leaky, attn dot, reduce over tg
    float2 bf[8], wa[8];
#pragma unroll
    for (int nt = 0; nt < 8; nt++) {
        int col = nt * 8 + 2 * tg;
        bf[nt] = *reinterpret_cast<const float2*>(b_feat + col);
        wa[nt] = *reinterpret_cast<const float2*>(W_attn + col);
    }

#pragma unroll
    for (int rh = 0; rh < 2; rh++) {
        int rl = m0 + rh * 8 + g;
        int e  = ebase + rl;
        int s = esrc[e], d = edst[e];
        const float* zsp = g_zsrc + s * D;
        const float* zdp = g_zdst + d * D;
        float p = 0.f;
#pragma unroll
        for (int nt = 0; nt < 8; nt++) {
            int col = nt * 8 + 2 * tg;
            float2 zs = *reinterpret_cast<const float2*>(zsp + col);
            float2 zd = *reinterpret_cast<const float2*>(zdp + col);
            float x0 = acc[nt][rh * 2]     + zs.x + zd.x + bf[nt].x;
            float x1 = acc[nt][rh * 2 + 1] + zs.y + zd.y + bf[nt].y;
            p += fmaxf(x0, 0.01f * x0) * wa[nt].x
               + fmaxf(x1, 0.01f * x1) * wa[nt].y;
        }
        p += __shfl_xor_sync(0xffffffffu, p, 1);
        p += __shfl_xor_sync(0xffffffffu, p, 2);
        if (tg == 0) g_e[e] = p;
    }
}

// ============================================================================
// K4: pull-based aggregation. One warp per dst node. Two passes over its CSR
// edge list: max, then exp-weighted sum (lane = 2 output columns). No float
// atomics anywhere; final write is coalesced and normalized.
// ============================================================================
__global__ void __launch_bounds__(256) gather_out(const int* __restrict__ esrc,
                                                  float* __restrict__ out) {
    int d = blockIdx.x * 8 + (threadIdx.x >> 5);
    if (d >= N_DST) return;
    const int lane = threadIdx.x & 31;
    const int beg = g_rowstart[d], end = g_rowstart[d + 1];

    // pass 1: segment max (lane-parallel over edges)
    float m = -3.4e38f;
    for (int i = beg + lane; i < end; i += 32)
        m = fmaxf(m, g_e[g_csr[i]]);
    m = fmaxf(m, __shfl_xor_sync(0xffffffffu, m, 16));
    m = fmaxf(m, __shfl_xor_sync(0xffffffffu, m, 8));
    m = fmaxf(m, __shfl_xor_sync(0xffffffffu, m, 4));
    m = fmaxf(m, __shfl_xor_sync(0xffffffffu, m, 2));
    m = fmaxf(m, __shfl_xor_sync(0xffffffffu, m, 1));

    // pass 2: serial over edges, lanes split the 64 columns (2 each)
    float acc0 = 0.f, acc1 = 0.f, den = 0.f;
    for (int i = beg; i < end; i++) {
        int eid = g_csr[i];                       // broadcast load
        float w = __expf(g_e[eid] - m);
        int s = esrc[eid];
        float2 z = *reinterpret_cast<const float2*>(g_zsrc + s * D + lane * 2);
        acc0 += w * z.x;
        acc1 += w * z.y;
        den  += w;
    }
    float inv = 1.f / fmaxf(den, 1e-9f);
    *reinterpret_cast<float2*>(out + (u64)d * D + lane * 2) =
        make_float2(acc0 * inv, acc1 * inv);
}

// ============================================================================
extern "C" void kernel_launch(void* const* d_in, const int* in_sizes, int n_in,
                              void* d_out, int out_size) {
    const float* h      = (const float*)d_in[0];
    const float* o      = (const float*)d_in[1];
    const float* tfidf  = (const float*)d_in[2];
    const float* W_fc   = (const float*)d_in[3];
    const float* W_fc1  = (const float*)d_in[4];
    const float* W_feat = (const float*)d_in[5];
    const float* b_feat = (const float*)d_in[6];
    const float* W_attn = (const float*)d_in[7];
    const int*   esrc   = (const int*)d_in[8];
    const int*   edst   = (const int*)d_in[9];
    float* out = (float*)d_out;

    const int EL_SMEM = (128 * 68 + 64 * 68) * 4;  // 52224 B
    cudaFuncSetAttribute(edge_logits_tc,
                         cudaFuncAttributeMaxDynamicSharedMemorySize, EL_SMEM);

    prep_kernel<<<(N_DST + 255) / 256, 256>>>(W_feat);
    hist_kernel<<<(NE + 255) / 256, 256>>>(edst);
    scan_kernel<<<1, 1024>>>();
    fill_kernel<<<(NE + 255) / 256, 256>>>(edst);
    rowgemm_zsrc<<<(N_SRC + 127) / 128, 128>>>(h, W_fc, N_SRC, IN_DIM);
    gemm_tf32_zdst<<<(N_DST + 63) / 64, 256>>>(o, W_fc1, N_DST, O_DIM);
    edge_logits_tc<<<NE / 128, 256, EL_SMEM>>>(tfidf, b_feat, W_attn, esrc, edst);
    gather_out<<<(N_DST + 7) / 8, 256>>>(esrc, out);
}

// round 5
// speedup vs baseline: 2.8263x; 1.0598x over previous
#include <cuda_runtime.h>

#define N_SRC  10000
#define N_DST  40000
#define NE     1280000
#define IN_DIM 128
#define D      64
#define FEAT   64
#define O_DIM  300

typedef unsigned long long u64;
typedef unsigned int u32;

// ---- scratch (static __device__ — no allocations anywhere) ----
__device__ __align__(16) float g_zsrc[N_SRC * D];   // 2.56 MB
__device__ __align__(16) float g_zdst[N_DST * D];   // 10.24 MB
__device__ float g_e2[NE];                          // logits in CSR order
__device__ int   g_srcperm[NE];                     // esrc in CSR order
__device__ __align__(16) float g_WT[FEAT * D];      // W_feat transposed [n][k]
__device__ int g_hist[N_DST];
__device__ int g_cursor[N_DST];
__device__ int g_rowstart[N_DST + 1];
__device__ int g_csr[NE];                           // edge id per CSR slot

// ---- helpers ----
__device__ __forceinline__ u64 pack2(float lo, float hi) {
    u64 r; asm("mov.b64 %0, {%1, %2};" : "=l"(r) : "f"(lo), "f"(hi)); return r;
}
__device__ __forceinline__ u64 fma2(u64 a, u64 b, u64 c) {
    u64 d; asm("fma.rn.f32x2 %0, %1, %2, %3;" : "=l"(d) : "l"(a), "l"(b), "l"(c)); return d;
}
__device__ __forceinline__ u32 cvt_tf32(float x) {
    u32 u; asm("cvt.rna.tf32.f32 %0, %1;" : "=r"(u) : "f"(x)); return u;
}
__device__ __forceinline__ uint4 cvt4(float4 v) {
    uint4 w; w.x = cvt_tf32(v.x); w.y = cvt_tf32(v.y);
    w.z = cvt_tf32(v.z); w.w = cvt_tf32(v.w); return w;
}
__device__ __forceinline__ void mma_tf32(float c[4], u32 a0, u32 a1, u32 a2, u32 a3,
                                         u32 b0, u32 b1) {
    asm("mma.sync.aligned.m16n8k8.row.col.f32.tf32.tf32.f32 "
        "{%0,%1,%2,%3}, {%4,%5,%6,%7}, {%8,%9}, {%0,%1,%2,%3};"
        : "+f"(c[0]), "+f"(c[1]), "+f"(c[2]), "+f"(c[3])
        : "r"(a0), "r"(a1), "r"(a2), "r"(a3), "r"(b0), "r"(b1));
}
__device__ __forceinline__ void ldsm4(u32& r0, u32& r1, u32& r2, u32& r3, u32 addr) {
    asm volatile("ldmatrix.sync.aligned.m8n8.x4.shared.b16 {%0,%1,%2,%3}, [%4];"
                 : "=r"(r0), "=r"(r1), "=r"(r2), "=r"(r3) : "r"(addr));
}

// ============================================================================
// prep: zero CSR counters; transpose W_feat -> g_WT[n][k]
// ============================================================================
__global__ void prep_kernel(const float* __restrict__ W_feat) {
    int i = blockIdx.x * 256 + threadIdx.x;
    if (i < N_DST) { g_hist[i] = 0; g_cursor[i] = 0; }
    if (i < FEAT * D) g_WT[(i & 63) * 64 + (i >> 6)] = W_feat[i];
}

__global__ void hist_kernel(const int* __restrict__ edst) {
    int i = blockIdx.x * blockDim.x + threadIdx.x;
    if (i < NE) atomicAdd(&g_hist[edst[i]], 1);
}

// single-block exclusive scan of g_hist -> g_rowstart
__global__ void __launch_bounds__(1024) scan_kernel() {
    __shared__ int part[1024];
    const int t = threadIdx.x;
    const int CH = 40;                       // 1024*40 = 40960 >= N_DST
    int own = 0;
    for (int j = 0; j < CH; j++) {
        int idx = t * CH + j;
        if (idx < N_DST) own += g_hist[idx];
    }
    part[t] = own;
    __syncthreads();
    for (int off = 1; off < 1024; off <<= 1) {
        int v = (t >= off) ? part[t - off] : 0;
        __syncthreads();
        part[t] += v;
        __syncthreads();
    }
    int base = part[t] - own;
    for (int j = 0; j < CH; j++) {
        int idx = t * CH + j;
        if (idx < N_DST) { g_rowstart[idx] = base; base += g_hist[idx]; }
    }
    if (t == 1023) g_rowstart[N_DST] = part[1023];
}

__global__ void fill_kernel(const int* __restrict__ edst) {
    int i = blockIdx.x * blockDim.x + threadIdx.x;
    if (i >= NE) return;
    int d = edst[i];
    int pos = atomicAdd(&g_cursor[d], 1);
    g_csr[g_rowstart[d] + pos] = i;
}

// ============================================================================
// K1: z_src = h @ W_fc, full fp32 (feeds output directly). M=10000, K=128.
// ============================================================================
__global__ void __launch_bounds__(128) rowgemm_zsrc(const float* __restrict__ A,
                                                    const float* __restrict__ B,
                                                    int M, int K) {
    __shared__ __align__(16) float As[128][33];
    __shared__ __align__(16) float Bs[32][64];
    int row = blockIdx.x * 128 + threadIdx.x;
    u64 acc[32];
#pragma unroll
    for (int i = 0; i < 32; i++) acc[i] = 0ull;

    for (int k0 = 0; k0 < K; k0 += 32) {
        __syncthreads();
        for (int idx = threadIdx.x; idx < 128 * 32; idx += 128) {
            int r = idx >> 5, c = idx & 31;
            int gr = blockIdx.x * 128 + r, gc = k0 + c;
            As[r][c] = (gr < M && gc < K) ? A[gr * K + gc] : 0.f;
        }
        for (int idx = threadIdx.x; idx < 32 * 64; idx += 128) {
            int r = idx >> 6, c = idx & 63;
            int gk = k0 + r;
            Bs[r][c] = (gk < K) ? B[gk * 64 + c] : 0.f;
        }
        __syncthreads();
#pragma unroll 4
        for (int kk = 0; kk < 32; kk++) {
            float t = As[threadIdx.x][kk];
            u64 tt = pack2(t, t);
            const ulonglong2* br = reinterpret_cast<const ulonglong2*>(&Bs[kk][0]);
#pragma unroll
            for (int i = 0; i < 16; i++) {
                ulonglong2 w = br[i];
                acc[2 * i]     = fma2(tt, w.x, acc[2 * i]);
                acc[2 * i + 1] = fma2(tt, w.y, acc[2 * i + 1]);
            }
        }
    }
    if (row < M) {
        u64* out = reinterpret_cast<u64*>(g_zsrc + row * D);
#pragma unroll
        for (int i = 0; i < 32; i++) out[i] = acc[i];
    }
}

// ============================================================================
// K2: z_dst = o @ W_fc1 via tf32 mma (logits-only, tf32 precision OK).
// ============================================================================
__global__ void __launch_bounds__(256) gemm_tf32_zdst(const float* __restrict__ A,
                                                      const float* __restrict__ B,
                                                      int M, int K) {
    __shared__ u32 Ts[64][68];
    __shared__ u32 Bs[64][72];

    const int tid  = threadIdx.x;
    const int warp = tid >> 5, lane = tid & 31;
    const int g = lane >> 2, tg = lane & 3;
    const int eg = warp >> 1, nh = warp & 1;
    const int rbase = blockIdx.x * 64;
    const int Kf4 = K >> 2;

    float acc[4][4];
#pragma unroll
    for (int nt = 0; nt < 4; nt++)
#pragma unroll
        for (int j = 0; j < 4; j++) acc[nt][j] = 0.f;

    const int KO = (K + 63) / 64;
    for (int ko = 0; ko < KO; ko++) {
        __syncthreads();
#pragma unroll
        for (int j = 0; j < 4; j++) {
            int idx = tid + j * 256;
            int r = idx >> 4, c4 = idx & 15;
            int gr = rbase + r, gf4 = ko * 16 + c4;
            float4 v = make_float4(0.f, 0.f, 0.f, 0.f);
            if (gr < M && gf4 < Kf4)
                v = reinterpret_cast<const float4*>(A + (u64)gr * K)[gf4];
            *reinterpret_cast<uint4*>(&Ts[r][c4 * 4]) = cvt4(v);
        }
#pragma unroll
        for (int j = 0; j < 4; j++) {
            int idx = tid + j * 256;
            int r = idx >> 4, c4 = idx & 15;
            int gk = ko * 64 + r;
            float4 v = make_float4(0.f, 0.f, 0.f, 0.f);
            if (gk < K)
                v = reinterpret_cast<const float4*>(B + gk * 64)[c4];
            *reinterpret_cast<uint4*>(&Bs[r][c4 * 4]) = cvt4(v);
        }
        __syncthreads();

        const int m0 = eg * 16;
#pragma unroll
        for (int kc = 0; kc < 8; kc++) {
            int k = kc * 8;
            u32 a0 = Ts[m0 + g][k + tg];
            u32 a1 = Ts[m0 + 8 + g][k + tg];
            u32 a2 = Ts[m0 + g][k + tg + 4];
            u32 a3 = Ts[m0 + 8 + g][k + tg + 4];
#pragma unroll
            for (int nt = 0; nt < 4; nt++) {
                int n0 = nh * 32 + nt * 8 + g;
                u32 b0 = Bs[k + tg][n0];
                u32 b1 = Bs[k + tg + 4][n0];
                mma_tf32(acc[nt], a0, a1, a2, a3, b0, b1);
            }
        }
    }

#pragma unroll
    for (int rh = 0; rh < 2; rh++) {
        int row = rbase + eg * 16 + rh * 8 + g;
        if (row < M) {
#pragma unroll
            for (int nt = 0; nt < 4; nt++) {
                int col = nh * 32 + nt * 8 + 2 * tg;
                float2 v = make_float2(acc[nt][rh * 2], acc[nt][rh * 2 + 1]);
                *reinterpret_cast<float2*>(g_zdst + row * D + col) = v;
            }
        }
    }
}

// ============================================================================
// K3: edge logits in CSR (dst-sorted) order. Block = CSR slots [b*128,(b+1)*128).
// Stage tfidf[csr[pos]] rows (gathered, 256B-aligned rows); dst repeats within
// a block -> zdst gathers hit L1/L2. Writes g_e2[pos] + g_srcperm[pos] coalesced.
// ============================================================================
__global__ void __launch_bounds__(256) edge_logits_tc(const float* __restrict__ tfidf,
                                                      const float* __restrict__ b_feat,
                                                      const float* __restrict__ W_attn,
                                                      const int* __restrict__ esrc,
                                                      const int* __restrict__ edst) {
    extern __shared__ u32 smbuf[];
    u32 (*Ts)[68] = reinterpret_cast<u32(*)[68]>(smbuf);            // [128][68]
    u32 (*Bs)[68] = reinterpret_cast<u32(*)[68]>(smbuf + 128 * 68); // [64][68]

    const int tid  = threadIdx.x;
    const int warp = tid >> 5, lane = tid & 31;
    const int g = lane >> 2, tg = lane & 3;
    const int pbase = blockIdx.x * 128;

    // stage gathered tfidf rows as tf32
#pragma unroll
    for (int j = 0; j < 8; j++) {
        int idx = tid + j * 256;
        int r = idx >> 4, c4 = idx & 15;
        int e = g_csr[pbase + r];
        float4 v = reinterpret_cast<const float4*>(tfidf + (u64)e * FEAT)[c4];
        *reinterpret_cast<uint4*>(&Ts[r][c4 * 4]) = cvt4(v);
    }
    // stage W_feat^T (n-major) as tf32
    {
        const float4* wt = reinterpret_cast<const float4*>(g_WT);
#pragma unroll
        for (int j = 0; j < 4; j++) {
            int idx = tid + j * 256;
            int r = idx >> 4, c4 = idx & 15;
            *reinterpret_cast<uint4*>(&Bs[r][c4 * 4]) = cvt4(wt[idx]);
        }
    }
    __syncthreads();

    const int m0 = warp * 16;
    const int q = lane >> 3, r8 = lane & 7;
    u32 aBase = (u32)__cvta_generic_to_shared(&Ts[m0 + ((q & 1) << 3) + r8][(q >> 1) << 2]);
    u32 bBase = (u32)__cvta_generic_to_shared(&Bs[((q >> 1) << 3) + r8][(q & 1) << 2]);
    const u32 GSTRIDE = 16 * 68 * 4;

    float acc[8][4];
#pragma unroll
    for (int nt = 0; nt < 8; nt++)
#pragma unroll
        for (int j = 0; j < 4; j++) acc[nt][j] = 0.f;

#pragma unroll
    for (int kc = 0; kc < 8; kc++) {
        u32 ko = kc * 32;
        u32 a0, a1, a2, a3;
        ldsm4(a0, a1, a2, a3, aBase + ko);
#pragma unroll
        for (int G = 0; G < 4; G++) {
            u32 b0, b1, b2, b3;
            ldsm4(b0, b1, b2, b3, bBase + G * GSTRIDE + ko);
            mma_tf32(acc[2 * G],     a0, a1, a2, a3, b0, b1);
            mma_tf32(acc[2 * G + 1], a0, a1, a2, a3, b2, b3);
        }
    }

    float2 bf[8], wa[8];
#pragma unroll
    for (int nt = 0; nt < 8; nt++) {
        int col = nt * 8 + 2 * tg;
        bf[nt] = *reinterpret_cast<const float2*>(b_feat + col);
        wa[nt] = *reinterpret_cast<const float2*>(W_attn + col);
    }

#pragma unroll
    for (int rh = 0; rh < 2; rh++) {
        int rl = m0 + rh * 8 + g;
        int pos = pbase + rl;
        int e = g_csr[pos];
        int s = esrc[e], d = edst[e];
        const float* zsp = g_zsrc + s * D;
        const float* zdp = g_zdst + d * D;
        float p = 0.f;
#pragma unroll
        for (int nt = 0; nt < 8; nt++) {
            int col = nt * 8 + 2 * tg;
            float2 zs = *reinterpret_cast<const float2*>(zsp + col);
            float2 zd = *reinterpret_cast<const float2*>(zdp + col);
            float x0 = acc[nt][rh * 2]     + zs.x + zd.x + bf[nt].x;
            float x1 = acc[nt][rh * 2 + 1] + zs.y + zd.y + bf[nt].y;
            p += fmaxf(x0, 0.01f * x0) * wa[nt].x
               + fmaxf(x1, 0.01f * x1) * wa[nt].y;
        }
        p += __shfl_xor_sync(0xffffffffu, p, 1);
        p += __shfl_xor_sync(0xffffffffu, p, 2);
        if (tg == 0) { g_e2[pos] = p; g_srcperm[pos] = s; }
    }
}

// ============================================================================
// K4: pull aggregation, fully streaming. One warp per dst node; g_e2/g_srcperm
// read sequentially; only zsrc row gather remains (L2-resident, 2.5 MB).
// ============================================================================
__global__ void __launch_bounds__(256) gather_out(float* __restrict__ out) {
    int d = blockIdx.x * 8 + (threadIdx.x >> 5);
    if (d >= N_DST) return;
    const int lane = threadIdx.x & 31;
    const int beg = g_rowstart[d], end = g_rowstart[d + 1];

    // pass 1: segment max (coalesced lane-strided reads)
    float m = -3.4e38f;
    for (int i = beg + lane; i < end; i += 32)
        m = fmaxf(m, g_e2[i]);
    m = fmaxf(m, __shfl_xor_sync(0xffffffffu, m, 16));
    m = fmaxf(m, __shfl_xor_sync(0xffffffffu, m, 8));
    m = fmaxf(m, __shfl_xor_sync(0xffffffffu, m, 4));
    m = fmaxf(m, __shfl_xor_sync(0xffffffffu, m, 2));
    m = fmaxf(m, __shfl_xor_sync(0xffffffffu, m, 1));

    // pass 2: serial over edges, lanes split 64 cols (2 each)
    float acc0 = 0.f, acc1 = 0.f, den = 0.f;
    for (int i = beg; i < end; i++) {
        float w = __expf(g_e2[i] - m);     // broadcast
        int s = g_srcperm[i];              // broadcast
        float2 z = *reinterpret_cast<const float2*>(g_zsrc + s * D + lane * 2);
        acc0 += w * z.x;
        acc1 += w * z.y;
        den  += w;
    }
    float inv = 1.f / fmaxf(den, 1e-9f);
    *reinterpret_cast<float2*>(out + (u64)d * D + lane * 2) =
        make_float2(acc0 * inv, acc1 * inv);
}

// ============================================================================
extern "C" void kernel_launch(void* const* d_in, const int* in_sizes, int n_in,
                              void* d_out, int out_size) {
    const float* h      = (const float*)d_in[0];
    const float* o      = (const float*)d_in[1];
    const float* tfidf  = (const float*)d_in[2];
    const float* W_fc   = (const float*)d_in[3];
    const float* W_fc1  = (const float*)d_in[4];
    const float* W_feat = (const float*)d_in[5];
    const float* b_feat = (const float*)d_in[6];
    const float* W_attn = (const float*)d_in[7];
    const int*   esrc   = (const int*)d_in[8];
    const int*   edst   = (const int*)d_in[9];
    float* out = (float*)d_out;

    const int EL_SMEM = (128 * 68 + 64 * 68) * 4;  // 52224 B
    cudaFuncSetAttribute(edge_logits_tc,
                         cudaFuncAttributeMaxDynamicSharedMemorySize, EL_SMEM);

    prep_kernel<<<(N_DST + 255) / 256, 256>>>(W_feat);
    hist_kernel<<<(NE + 255) / 256, 256>>>(edst);
    scan_kernel<<<1, 1024>>>();
    fill_kernel<<<(NE + 255) / 256, 256>>>(edst);
    rowgemm_zsrc<<<(N_SRC + 127) / 128, 128>>>(h, W_fc, N_SRC, IN_DIM);
    gemm_tf32_zdst<<<(N_DST + 63) / 64, 256>>>(o, W_fc1, N_DST, O_DIM);
    edge_logits_tc<<<NE / 128, 256, EL_SMEM>>>(tfidf, b_feat, W_attn, esrc, edst);
    gather_out<<<(N_DST + 7) / 8, 256>>>(out);
}